// round 6
// baseline (speedup 1.0000x reference)
#include <cuda_runtime.h>
#include <cuda_bf16.h>

#define HID 256
#define GAMMA_F 12.0f
#define BATCH 8
#define NBLOCKS 296
#define NTHREADS 256

__device__ float g_scores[BATCH * 100000];  // S[e*8+b], 3.2MB (L2-resident)

// Replay-safe grid barrier: generation counter only ever increases; count
// resets to 0 inside each barrier episode.
__device__ unsigned g_count = 0;
__device__ unsigned g_gen = 0;

__device__ __forceinline__ void grid_barrier(int nblocks) {
    __syncthreads();
    if (threadIdx.x == 0) {
        const unsigned gen = *((volatile unsigned*)&g_gen);
        __threadfence();                       // make phase-1 writes visible
        const unsigned arr = atomicAdd(&g_count, 1);
        if (arr == (unsigned)nblocks - 1) {
            g_count = 0;                       // safe: no one reads it again
            __threadfence();
            atomicAdd(&g_gen, 1);              // release
        } else {
            while (*((volatile unsigned*)&g_gen) == gen) { }
        }
        __threadfence();                       // acquire side
    }
    __syncthreads();
}

__global__ void __launch_bounds__(NTHREADS, 2)
kge_fused_kernel(const float* __restrict__ ent,
                 const float* __restrict__ rel,
                 const int*   __restrict__ pos,
                 const int*   __restrict__ neg,
                 float*       __restrict__ out,
                 int ne, int nneg)
{
    const int lane = threadIdx.x & 31;
    const int warp = threadIdx.x >> 5;
    float* const scores = g_scores;

    // ---------------- Phase 1: score all entities vs all 8 hr vectors ------
    // hrs = 2*(head + relation); lane owns dims [lane*8, lane*8+8).
    float hrs[BATCH][8];
#pragma unroll
    for (int b = 0; b < BATCH; b++) {
        const int hidx = pos[b * 3 + 0];
        const int ridx = pos[b * 3 + 1];
        const float4* h4 = reinterpret_cast<const float4*>(ent + (size_t)hidx * HID);
        const float4* r4 = reinterpret_cast<const float4*>(rel + (size_t)ridx * HID);
        float4 h0 = h4[lane * 2], h1 = h4[lane * 2 + 1];
        float4 r0 = r4[lane * 2], r1 = r4[lane * 2 + 1];
        hrs[b][0] = 2.0f * (h0.x + r0.x);  hrs[b][1] = 2.0f * (h0.y + r0.y);
        hrs[b][2] = 2.0f * (h0.z + r0.z);  hrs[b][3] = 2.0f * (h0.w + r0.w);
        hrs[b][4] = 2.0f * (h1.x + r1.x);  hrs[b][5] = 2.0f * (h1.y + r1.y);
        hrs[b][6] = 2.0f * (h1.z + r1.z);  hrs[b][7] = 2.0f * (h1.w + r1.w);
    }

    const bool hi16 = (lane & 16) != 0;
    const bool hi8  = (lane & 8)  != 0;
    const bool hi4  = (lane & 4)  != 0;

    // Contiguous row chunk per warp.
    const int gw = blockIdx.x * (NTHREADS >> 5) + warp;
    const int W  = gridDim.x * (NTHREADS >> 5);
    const int per   = ne / W;
    const int rem   = ne % W;
    const int start = gw * per + (gw < rem ? gw : rem);
    const int end   = start + per + (gw < rem ? 1 : 0);

    float e[8], p[8];
    if (start < end) {
        const float4* er = reinterpret_cast<const float4*>(ent + (size_t)start * HID);
        float4 x = er[lane * 2], y = er[lane * 2 + 1];
        e[0]=x.x; e[1]=x.y; e[2]=x.z; e[3]=x.w;
        e[4]=y.x; e[5]=y.y; e[6]=y.z; e[7]=y.w;
    }

    for (int row = start; row < end; row++) {
        if (row + 1 < end) {  // prefetch next row
            const float4* pr = reinterpret_cast<const float4*>(ent + (size_t)(row + 1) * HID);
            float4 x = pr[lane * 2], y = pr[lane * 2 + 1];
            p[0]=x.x; p[1]=x.y; p[2]=x.z; p[3]=x.w;
            p[4]=y.x; p[5]=y.y; p[6]=y.z; p[7]=y.w;
        }

        float v[BATCH];
#pragma unroll
        for (int b = 0; b < BATCH; b++) {
            float acc = 0.0f;
#pragma unroll
            for (int j = 0; j < 8; j++) {
                // FFMA-imm (rt1): d2 = hrs - 2*e = 2*(hr - e)
                const float d2 = __fmaf_rn(e[j], -2.0f, hrs[b][j]);
                acc += fabsf(d2);              // FADD acc, acc, |d2|  (rt2)
            }
            v[b] = acc;                        // = 2 * sum|hr-e| for lane dims
        }

        // Folding reduction: lane group (lane>>2) ends with batch (lane>>2).
#pragma unroll
        for (int j = 0; j < 4; j++) {
            const float send = hi16 ? v[j] : v[j + 4];
            const float recv = __shfl_xor_sync(0xFFFFFFFFu, send, 16);
            v[j] = (hi16 ? v[j + 4] : v[j]) + recv;
        }
#pragma unroll
        for (int j = 0; j < 2; j++) {
            const float send = hi8 ? v[j] : v[j + 2];
            const float recv = __shfl_xor_sync(0xFFFFFFFFu, send, 8);
            v[j] = (hi8 ? v[j + 2] : v[j]) + recv;
        }
        {
            const float send = hi4 ? v[0] : v[1];
            const float recv = __shfl_xor_sync(0xFFFFFFFFu, send, 4);
            v[0] = (hi4 ? v[1] : v[0]) + recv;
        }
        v[0] += __shfl_xor_sync(0xFFFFFFFFu, v[0], 2);
        v[0] += __shfl_xor_sync(0xFFFFFFFFu, v[0], 1);

        if ((lane & 3) == 0)  // score = gamma - 0.5*sum2  (FFMA-imm)
            scores[(size_t)row * BATCH + (lane >> 2)] =
                __fmaf_rn(v[0], -0.5f, GAMMA_F);

#pragma unroll
        for (int j = 0; j < 8; j++) e[j] = p[j];
    }

    // ---------------- Barrier: scores visible to all blocks ----------------
    grid_barrier(gridDim.x);

    // ---------------- Phase 2: out[b][n] = scores[neg[b][n]*8 + b] ---------
    // Scores table (3.2MB) is hot in L2 now.
    const int n4   = nneg >> 2;
    const int jobs = BATCH * n4;
    const int nthr = gridDim.x * NTHREADS;
    const int gtid = blockIdx.x * NTHREADS + threadIdx.x;

    for (int j = gtid; j < jobs; j += nthr) {
        const int b = j / n4;
        const int t = j - b * n4;
        const int4 idx = reinterpret_cast<const int4*>(neg + (size_t)b * nneg)[t];
        float4 r;
        r.x = scores[(size_t)idx.x * BATCH + b];
        r.y = scores[(size_t)idx.y * BATCH + b];
        r.z = scores[(size_t)idx.z * BATCH + b];
        r.w = scores[(size_t)idx.w * BATCH + b];
        reinterpret_cast<float4*>(out + (size_t)b * nneg)[t] = r;
    }
    // Tail elements (nneg % 4) — none for nneg=100000, but stay general.
    const int tail_start = n4 * 4;
    for (int j = gtid; j < BATCH * (nneg - tail_start); j += nthr) {
        const int b = j / (nneg - tail_start);
        const int n = tail_start + (j - b * (nneg - tail_start));
        out[(size_t)b * nneg + n] = scores[(size_t)neg[(size_t)b * nneg + n] * BATCH + b];
    }
}

extern "C" void kernel_launch(void* const* d_in, const int* in_sizes, int n_in,
                              void* d_out, int out_size)
{
    const float* ent = (const float*)d_in[0];  // [NE, 256] f32
    const float* rel = (const float*)d_in[1];  // [NR, 256] f32
    const int*   pos = (const int*)d_in[2];    // [B, 3] i32
    const int*   neg = (const int*)d_in[3];    // [B, N] i32
    float*       out = (float*)d_out;          // [B, N] f32

    const int batch = in_sizes[2] / 3;         // 8
    const int nneg  = in_sizes[3] / batch;     // 100000
    const int ne    = in_sizes[0] / HID;       // 100000
    (void)batch;

    // 296 blocks x 256 threads: exactly one resident wave at 2 CTA/SM
    // (>=148 SMs), required for the grid barrier.
    kge_fused_kernel<<<NBLOCKS, NTHREADS>>>(ent, rel, pos, neg, out, ne, nneg);
}